// round 11
// baseline (speedup 1.0000x reference)
#include <cuda_runtime.h>
#include <cuda_fp16.h>
#include <cuda_bf16.h>
#include <mma.h>
#include <math.h>

using namespace nvcuda;

#define NN 50000
#define DD 128
#define EE 800000
#define NCHUNK 49   // ceil(50000/1024)

#define APITCH 136  // half pitch (272B = 17 uint4) for fp16 smem tiles
#define CPITCH 132  // float pitch for C smem tile
#define GTM 64      // gemm M tile (rows per CTA)
#define NTILE 782   // ceil(50000/64)

// -------- device scratch (no runtime allocation allowed) --------
__device__ float  g_b[2 * NN];                 // boundary scores
__device__ __half g_t[2 * (size_t)NN * DD];    // transformed features (fp16)
__device__ __half g_updh[2 * (size_t)NN * DD]; // x + aggregated messages (fp16)
__device__ __half g_etW1h[2 * 128 * 128];
__device__ __half g_etW2h[2 * 128 * 128];
__device__ __half g_nuWh[2 * 128 * 128];
__device__ int    g_cnt[2 * NN];
__device__ int    g_off[2 * NN];
__device__ int    g_cur[2 * NN];
__device__ int    g_bsum[2 * 64];
__device__ int    g_srcA[2 * (size_t)EE];      // CSR-ordered src ids
__device__ float  g_eaA[2 * (size_t)EE];       // CSR-ordered raw edge attrs

// ---------------------------------------------------------------
__global__ void prep_kernel() {
    int i = blockIdx.x * blockDim.x + threadIdx.x;
    if (i < 2 * NN) g_cnt[i] = 0;
}

// weights f32 -> f16 (once)
__global__ void convw_kernel(const float* __restrict__ etW1,
                             const float* __restrict__ etW2,
                             const float* __restrict__ nuW) {
    int i = blockIdx.x * 256 + threadIdx.x;   // each thread: 4 floats
    const int per = 2 * 128 * 128 / 4;        // 8192
    const float* src; __half* dst; int k;
    if (i < per)            { src = etW1; dst = g_etW1h; k = i; }
    else if (i < 2 * per)   { src = etW2; dst = g_etW2h; k = i - per; }
    else if (i < 3 * per)   { src = nuW;  dst = g_nuWh;  k = i - 2 * per; }
    else return;
    float4 v = ((const float4*)src)[k];
    __half2* d = (__half2*)dst + (size_t)k * 2;
    d[0] = __floats2half2_rn(v.x, v.y);
    d[1] = __floats2half2_rn(v.z, v.w);
}

__global__ __launch_bounds__(256) void hist_kernel(const int* __restrict__ ei) {
    int type = blockIdx.y;
    int j = blockIdx.x * 256 + threadIdx.x;
    if (j >= EE) return;
    int d = ei[(size_t)type * 2 * EE + EE + j];
    atomicAdd(&g_cnt[type * NN + d], 1);
}

// ---------------------------------------------------------------
// decoupled 3-phase exclusive scan
// ---------------------------------------------------------------
__global__ __launch_bounds__(1024) void scan1_kernel() {
    __shared__ int warpsums[32];
    int type = blockIdx.y, chunk = blockIdx.x;
    int tid = threadIdx.x, lane = tid & 31, wid = tid >> 5;
    int idx = chunk * 1024 + tid;
    int v = (idx < NN) ? g_cnt[type * NN + idx] : 0;
    int inc = v;
#pragma unroll
    for (int o = 1; o < 32; o <<= 1) {
        int y = __shfl_up_sync(0xffffffffu, inc, o);
        if (lane >= o) inc += y;
    }
    if (lane == 31) warpsums[wid] = inc;
    __syncthreads();
    if (tid < 32) {
        int w = warpsums[tid];
        int s = w;
#pragma unroll
        for (int o = 1; o < 32; o <<= 1) {
            int y = __shfl_up_sync(0xffffffffu, s, o);
            if (tid >= o) s += y;
        }
        warpsums[tid] = s - w;
    }
    __syncthreads();
    int excl = inc - v + warpsums[wid];
    if (idx < NN) g_off[type * NN + idx] = excl;
    if (tid == 1023) g_bsum[type * 64 + chunk] = excl + v;
}

__global__ void scan2_kernel() {
    int type = threadIdx.x;
    if (type < 2) {
        int run = 0;
        for (int c = 0; c < NCHUNK; c++) {
            int v = g_bsum[type * 64 + c];
            g_bsum[type * 64 + c] = run;
            run += v;
        }
    }
}

__global__ __launch_bounds__(1024) void scan3_kernel() {
    int type = blockIdx.y, chunk = blockIdx.x;
    int idx = chunk * 1024 + threadIdx.x;
    if (idx < NN) {
        int o = g_off[type * NN + idx] + g_bsum[type * 64 + chunk];
        g_off[type * NN + idx] = o;
        g_cur[type * NN + idx] = o;
    }
}

// ---------------------------------------------------------------
// bin: write (src, ea) into CSR slot by destination (no MLP here)
// ---------------------------------------------------------------
__global__ __launch_bounds__(256) void bin_kernel(const int* __restrict__ ei,
                                                  const float* __restrict__ ea) {
    int type = blockIdx.y;
    int j = blockIdx.x * 256 + threadIdx.x;
    if (j >= EE) return;
    const int* eib = ei + (size_t)type * 2 * EE;
    int s = eib[j];
    int d = eib[EE + j];
    int pos = atomicAdd(&g_cur[type * NN + d], 1);
    g_srcA[(size_t)type * EE + pos] = s;
    g_eaA[(size_t)type * EE + pos] = ea[(size_t)type * EE + j];
}

// ---------------------------------------------------------------
// boundary MLP (fp32, deliberately: feeds discontinuous >0.3 branch)
// ---------------------------------------------------------------
__global__ __launch_bounds__(128) void boundary_kernel(
    const float* __restrict__ x,
    const float* __restrict__ bdW1, const float* __restrict__ bdb1,
    const float* __restrict__ bdW2, const float* __restrict__ bdb2,
    const float* __restrict__ bdW3, const float* __restrict__ bdb3)
{
    __shared__ float W1s[128 * 64];
    __shared__ float W2s[64 * 32];
    __shared__ float W3s[32];
    __shared__ float b1s[64], b2s[32];
    __shared__ float b3s;

    int type = blockIdx.y;
    int tid = threadIdx.x;
    const float* W1 = bdW1 + (size_t)type * 128 * 64;
    const float* W2 = bdW2 + (size_t)type * 64 * 32;
    for (int i = tid; i < 128 * 64; i += 128) W1s[i] = W1[i];
    for (int i = tid; i < 64 * 32; i += 128) W2s[i] = W2[i];
    if (tid < 32) W3s[tid] = bdW3[type * 32 + tid];
    if (tid < 64) b1s[tid] = bdb1[type * 64 + tid];
    if (tid < 32) b2s[tid] = bdb2[type * 32 + tid];
    if (tid == 0) b3s = bdb3[type];
    __syncthreads();

    int node = blockIdx.x * 128 + tid;
    if (node >= NN) return;

    const float4* xr = (const float4*)(x + ((size_t)type * NN + node) * DD);

    float h1[64];
#pragma unroll
    for (int j = 0; j < 64; j++) h1[j] = b1s[j];

    for (int d4 = 0; d4 < 32; d4++) {
        float4 xv = xr[d4];
        float vs[4] = {xv.x, xv.y, xv.z, xv.w};
#pragma unroll
        for (int dd = 0; dd < 4; dd++) {
            float v = vs[dd];
            const float4* wr = (const float4*)&W1s[(d4 * 4 + dd) * 64];
#pragma unroll
            for (int q = 0; q < 16; q++) {
                float4 w = wr[q];
                h1[q * 4 + 0] += v * w.x;
                h1[q * 4 + 1] += v * w.y;
                h1[q * 4 + 2] += v * w.z;
                h1[q * 4 + 3] += v * w.w;
            }
        }
    }
#pragma unroll
    for (int j = 0; j < 64; j++) h1[j] = fmaxf(h1[j], 0.f);

    float h2[32];
#pragma unroll
    for (int j = 0; j < 32; j++) h2[j] = b2s[j];
#pragma unroll
    for (int k = 0; k < 64; k++) {
        float v = h1[k];
        const float4* wr = (const float4*)&W2s[k * 32];
#pragma unroll
        for (int q = 0; q < 8; q++) {
            float4 w = wr[q];
            h2[q * 4 + 0] += v * w.x;
            h2[q * 4 + 1] += v * w.y;
            h2[q * 4 + 2] += v * w.z;
            h2[q * 4 + 3] += v * w.w;
        }
    }
    float z = b3s;
#pragma unroll
    for (int k = 0; k < 32; k++) z += fmaxf(h2[k], 0.f) * W3s[k];

    g_b[type * NN + node] = 1.f / (1.f + expf(-z));
}

// ---------------------------------------------------------------
// wmma helpers — warp tiling 2(M) x 4(N): B-panel smem dup 2x (was 4x)
// ---------------------------------------------------------------
__device__ __forceinline__ void wmma_tile64(
    const __half* Ah, const __half* Bh, float* Cs, int wid)
{
    int wm = wid & 1, wn = wid >> 1;    // wm: 2x32 rows, wn: 4x32 cols
    wmma::fragment<wmma::accumulator, 16, 16, 16, float> acc[2][2];
#pragma unroll
    for (int i = 0; i < 2; i++)
#pragma unroll
        for (int j = 0; j < 2; j++) wmma::fill_fragment(acc[i][j], 0.f);

#pragma unroll
    for (int k = 0; k < 8; k++) {
        wmma::fragment<wmma::matrix_a, 16, 16, 16, __half, wmma::row_major> a[2];
        wmma::fragment<wmma::matrix_b, 16, 16, 16, __half, wmma::row_major> b[2];
#pragma unroll
        for (int i = 0; i < 2; i++)
            wmma::load_matrix_sync(a[i], Ah + (wm * 32 + i * 16) * APITCH + k * 16, APITCH);
#pragma unroll
        for (int j = 0; j < 2; j++)
            wmma::load_matrix_sync(b[j], Bh + (k * 16) * APITCH + wn * 32 + j * 16, APITCH);
#pragma unroll
        for (int i = 0; i < 2; i++)
#pragma unroll
            for (int j = 0; j < 2; j++)
                wmma::mma_sync(acc[i][j], a[i], b[j], acc[i][j]);
    }
#pragma unroll
    for (int i = 0; i < 2; i++)
#pragma unroll
        for (int j = 0; j < 2; j++)
            wmma::store_matrix_sync(Cs + (wm * 32 + i * 16) * CPITCH + wn * 32 + j * 16,
                                    acc[i][j], CPITCH, wmma::mem_row_major);
}

// A-tile loader with inline f32->f16 conversion (x touched once per row)
__device__ __forceinline__ void load_rows_f32_h16(
    __half* dst, const float* src, int row0, int rowlim, int tid)
{
    for (int idx = tid; idx < 64 * 32; idx += 256) {
        int r = idx >> 5, c4 = idx & 31;
        int row = row0 + r;
        float4 v = (row < rowlim) ? ((const float4*)(src + (size_t)row * DD))[c4]
                                  : make_float4(0.f, 0.f, 0.f, 0.f);
        __half2* d = (__half2*)&dst[r * APITCH + c4 * 4];
        d[0] = __floats2half2_rn(v.x, v.y);
        d[1] = __floats2half2_rn(v.z, v.w);
    }
}

__device__ __forceinline__ void copy_rows_h16(
    __half* dst, const __half* src, int row0, int rowlim, int tid)
{
    uint4* d = (uint4*)dst;
    const uint4* s = (const uint4*)src;
    for (int i = tid; i < 64 * 16; i += 256) {
        int r = i >> 4, c = i & 15;
        int row = row0 + r;
        uint4 v = make_uint4(0u, 0u, 0u, 0u);
        if (row < rowlim) v = s[(size_t)row * 16 + c];
        d[r * 17 + c] = v;                    // APITCH = 136 halves = 17 uint4
    }
}

__device__ __forceinline__ void copy_w_h16(
    __half* dst, const __half* src, int tid)
{
    uint4* d = (uint4*)dst;
    const uint4* s = (const uint4*)src;
    for (int i = tid; i < 128 * 16; i += 256) {
        int r = i >> 4, c = i & 15;
        d[r * 17 + c] = s[r * 16 + c];
    }
}

// ---------------------------------------------------------------
// et (tensor core): t = relu(x @ W1 + b1) @ W2 + b2  -> g_t (fp16)
// both weight tiles resident; Cs aliases B1h (dead after mma1)
// ---------------------------------------------------------------
__global__ __launch_bounds__(256, 2) void et_wmma_kernel(
    const float* __restrict__ x,
    const float* __restrict__ b1g, const float* __restrict__ b2g)
{
    extern __shared__ char smem_raw[];
    __half* Ah  = (__half*)smem_raw;           // 64*APITCH
    __half* B1h = Ah + 64 * APITCH;            // 128*APITCH
    __half* B2h = B1h + 128 * APITCH;          // 128*APITCH
    float*  Cs  = (float*)B1h;                 // alias (33792B <= 34816B)

    int type = blockIdx.y;
    int m0 = blockIdx.x * GTM;
    int tid = threadIdx.x;
    int wid = tid >> 5;
    int wm = wid & 1, wn = wid >> 1;

    load_rows_f32_h16(Ah, x + (size_t)type * NN * DD, m0, NN, tid);
    copy_w_h16(B1h, g_etW1h + type * 128 * 128, tid);
    copy_w_h16(B2h, g_etW2h + type * 128 * 128, tid);
    __syncthreads();

    // mma1: compute into register fragments, delay store until all B1 reads done
    wmma::fragment<wmma::accumulator, 16, 16, 16, float> acc[2][2];
#pragma unroll
    for (int i = 0; i < 2; i++)
#pragma unroll
        for (int j = 0; j < 2; j++) wmma::fill_fragment(acc[i][j], 0.f);
#pragma unroll
    for (int k = 0; k < 8; k++) {
        wmma::fragment<wmma::matrix_a, 16, 16, 16, __half, wmma::row_major> a[2];
        wmma::fragment<wmma::matrix_b, 16, 16, 16, __half, wmma::row_major> b[2];
#pragma unroll
        for (int i = 0; i < 2; i++)
            wmma::load_matrix_sync(a[i], Ah + (wm * 32 + i * 16) * APITCH + k * 16, APITCH);
#pragma unroll
        for (int j = 0; j < 2; j++)
            wmma::load_matrix_sync(b[j], B1h + (k * 16) * APITCH + wn * 32 + j * 16, APITCH);
#pragma unroll
        for (int i = 0; i < 2; i++)
#pragma unroll
            for (int j = 0; j < 2; j++)
                wmma::mma_sync(acc[i][j], a[i], b[j], acc[i][j]);
    }
    __syncthreads();   // all warps done reading B1h
#pragma unroll
    for (int i = 0; i < 2; i++)
#pragma unroll
        for (int j = 0; j < 2; j++)
            wmma::store_matrix_sync(Cs + (wm * 32 + i * 16) * CPITCH + wn * 32 + j * 16,
                                    acc[i][j], CPITCH, wmma::mem_row_major);
    __syncthreads();

    // bias + relu -> Ah (fp16)
    const float* b1 = b1g + type * 128;
    for (int idx = tid; idx < 64 * 64; idx += 256) {
        int r = idx >> 6, c2 = (idx & 63) * 2;
        float z0 = Cs[r * CPITCH + c2]     + b1[c2];
        float z1 = Cs[r * CPITCH + c2 + 1] + b1[c2 + 1];
        *(__half2*)&Ah[r * APITCH + c2] = __floats2half2_rn(fmaxf(z0, 0.f), fmaxf(z1, 0.f));
    }
    __syncthreads();

    // mma2: B2h reads, store to Cs (aliases B1h only — safe)
    wmma_tile64(Ah, B2h, Cs, wid);
    __syncthreads();

    const float* b2 = b2g + type * 128;
    __half2* tb = (__half2*)(g_t + (size_t)type * NN * DD);
    for (int idx = tid; idx < 64 * 64; idx += 256) {
        int r = idx >> 6, c2idx = idx & 63;
        int row = m0 + r;
        if (row < NN) {
            int c2 = c2idx * 2;
            float z0 = Cs[r * CPITCH + c2]     + b2[c2];
            float z1 = Cs[r * CPITCH + c2 + 1] + b2[c2 + 1];
            tb[(size_t)row * 64 + c2idx] = __floats2half2_rn(z0, z1);
        }
    }
}

// ---------------------------------------------------------------
// gather + fused edge-weight MLP:
// updh[to][n] = fp16(x[to][n] + sum_e c_e * t[src_e])
// phase A: lane=edge, compute c (fp32 MLP identical to reference)
// phase B: shfl-broadcast (src,c), accumulate 4-way unrolled
// ---------------------------------------------------------------
__global__ __launch_bounds__(256) void gather_kernel(
    const float* __restrict__ x,
    const float* __restrict__ bwW1, const float* __restrict__ bwb1,
    const float* __restrict__ bwW2, const float* __restrict__ bwb2,
    const float* __restrict__ bwW3, const float* __restrict__ bwb3)
{
    __shared__ float W1s[64], B1s[32], W2s[512], B2s[16], W3s[16];
    __shared__ float B3s;

    int to = blockIdx.y;
    int e = 1 - to;                 // edge type landing on node type `to`
    int tid = threadIdx.x;

    if (tid < 64) W1s[tid] = bwW1[e * 64 + tid];
    if (tid < 32) B1s[tid] = bwb1[e * 32 + tid];
    for (int i = tid; i < 512; i += 256) W2s[i] = bwW2[e * 512 + i];
    if (tid < 16) B2s[tid] = bwb2[e * 16 + tid];
    if (tid < 16) W3s[tid] = bwW3[e * 16 + tid];
    if (tid == 0) B3s = bwb3[e];
    __syncthreads();

    int lane = tid & 31;
    int warp = tid >> 5;
    int n = blockIdx.x * 8 + warp;
    if (n >= NN) return;

    int base0 = e * NN + n;
    int st = g_off[base0];
    int en = g_cur[base0];

    float db = g_b[to * NN + n];    // dst boundary score (node type to)
    bool dbhigh = db > 0.3f;

    const uint2* tb = (const uint2*)(g_t + (size_t)e * NN * DD);
    const int* srcp = g_srcA + (size_t)e * EE;
    const float* eap = g_eaA + (size_t)e * EE;

    float4 acc = ((const float4*)(x + ((size_t)to * NN + n) * DD))[lane];

    for (int base = st; base < en; base += 32) {
        int j = base + lane;
        bool valid = j < en;
        int s_l = valid ? __ldg(srcp + j) : 0;
        float ea_l = valid ? __ldg(eap + j) : 0.f;
        float sb = valid ? g_b[e * NN + s_l] : 0.f;

        // fp32 MLP (same ops/order as reference coef path)
        float h1[32];
#pragma unroll
        for (int q = 0; q < 32; q++)
            h1[q] = fmaxf(sb * W1s[q] + db * W1s[32 + q] + B1s[q], 0.f);

        float4 h2v[4];
#pragma unroll
        for (int p = 0; p < 4; p++) h2v[p] = ((const float4*)B2s)[p];
        const float4* W2v = (const float4*)W2s;
#pragma unroll
        for (int q = 0; q < 32; q++) {
            float v = h1[q];
#pragma unroll
            for (int p = 0; p < 4; p++) {
                float4 w = W2v[q * 4 + p];
                h2v[p].x += v * w.x;
                h2v[p].y += v * w.y;
                h2v[p].z += v * w.z;
                h2v[p].w += v * w.w;
            }
        }
        float z = B3s;
#pragma unroll
        for (int p = 0; p < 4; p++) {
            z += fmaxf(h2v[p].x, 0.f) * W3s[p * 4 + 0];
            z += fmaxf(h2v[p].y, 0.f) * W3s[p * 4 + 1];
            z += fmaxf(h2v[p].z, 0.f) * W3s[p * 4 + 2];
            z += fmaxf(h2v[p].w, 0.f) * W3s[p * 4 + 3];
        }
        float w = 1.f / (1.f + expf(-z));
        if (sb > 0.3f || dbhigh) w *= 2.f;
        float c_l = ea_l * w;

        // phase B: broadcast and accumulate
        int cnt = min(32, en - base);
        int jj = 0;
        for (; jj + 3 < cnt; jj += 4) {
            int   s0 = __shfl_sync(0xffffffffu, s_l, jj);
            int   s1 = __shfl_sync(0xffffffffu, s_l, jj + 1);
            int   s2 = __shfl_sync(0xffffffffu, s_l, jj + 2);
            int   s3 = __shfl_sync(0xffffffffu, s_l, jj + 3);
            float c0 = __shfl_sync(0xffffffffu, c_l, jj);
            float c1 = __shfl_sync(0xffffffffu, c_l, jj + 1);
            float c2 = __shfl_sync(0xffffffffu, c_l, jj + 2);
            float c3 = __shfl_sync(0xffffffffu, c_l, jj + 3);
            uint2 h0 = tb[(size_t)s0 * 32 + lane];
            uint2 h1b = tb[(size_t)s1 * 32 + lane];
            uint2 h2 = tb[(size_t)s2 * 32 + lane];
            uint2 h3 = tb[(size_t)s3 * 32 + lane];
            float2 a0 = __half22float2(*(__half2*)&h0.x),  b0 = __half22float2(*(__half2*)&h0.y);
            float2 a1 = __half22float2(*(__half2*)&h1b.x), b1 = __half22float2(*(__half2*)&h1b.y);
            float2 a2 = __half22float2(*(__half2*)&h2.x),  b2 = __half22float2(*(__half2*)&h2.y);
            float2 a3 = __half22float2(*(__half2*)&h3.x),  b3 = __half22float2(*(__half2*)&h3.y);
            acc.x += a0.x * c0; acc.y += a0.y * c0; acc.z += b0.x * c0; acc.w += b0.y * c0;
            acc.x += a1.x * c1; acc.y += a1.y * c1; acc.z += b1.x * c1; acc.w += b1.y * c1;
            acc.x += a2.x * c2; acc.y += a2.y * c2; acc.z += b2.x * c2; acc.w += b2.y * c2;
            acc.x += a3.x * c3; acc.y += a3.y * c3; acc.z += b3.x * c3; acc.w += b3.y * c3;
        }
        for (; jj < cnt; jj++) {
            int   s0 = __shfl_sync(0xffffffffu, s_l, jj);
            float c0 = __shfl_sync(0xffffffffu, c_l, jj);
            uint2 h0 = tb[(size_t)s0 * 32 + lane];
            float2 a0 = __half22float2(*(__half2*)&h0.x), b0 = __half22float2(*(__half2*)&h0.y);
            acc.x += a0.x * c0; acc.y += a0.y * c0; acc.z += b0.x * c0; acc.w += b0.y * c0;
        }
    }

    __half2 p0 = __floats2half2_rn(acc.x, acc.y);
    __half2 p1 = __floats2half2_rn(acc.z, acc.w);
    uint2 u;
    u.x = *(unsigned*)&p0;
    u.y = *(unsigned*)&p1;
    ((uint2*)(g_updh + ((size_t)to * NN + n) * DD))[lane] = u;
}

// ---------------------------------------------------------------
// nu (tensor core): out = relu(LN(updh @ nuW + nub) * g + b)
// ---------------------------------------------------------------
__global__ __launch_bounds__(256, 2) void nu_wmma_kernel(
    const float* __restrict__ nub,
    const float* __restrict__ lng, const float* __restrict__ lnb,
    float* __restrict__ out)
{
    extern __shared__ char smem_raw[];
    __half* Ah = (__half*)smem_raw;
    __half* Bh = Ah + 64 * APITCH;
    float*  Cs = (float*)(Bh + 128 * APITCH);
    float*  nubS = Cs + 64 * CPITCH;    // 128
    float*  gS   = nubS + 128;          // 128
    float*  lbS  = gS + 128;            // 128

    int type = blockIdx.y;
    int m0 = blockIdx.x * GTM;
    int tid = threadIdx.x;
    int wid = tid >> 5;
    int lane = tid & 31;

    copy_rows_h16(Ah, g_updh + (size_t)type * NN * DD, m0, NN, tid);
    copy_w_h16(Bh, g_nuWh + type * 128 * 128, tid);
    if (tid < 128) {
        nubS[tid] = nub[type * 128 + tid];
        gS[tid]   = lng[type * 128 + tid];
        lbS[tid]  = lnb[type * 128 + tid];
    }
    __syncthreads();

    wmma_tile64(Ah, Bh, Cs, wid);
    __syncthreads();

    // LN + relu epilogue: warp per 8 rows, lane owns 4 columns
    float* ob = out + (size_t)type * NN * DD;
    float4 bb = ((const float4*)nubS)[lane];
    float4 gg = ((const float4*)gS)[lane];
    float4 ll = ((const float4*)lbS)[lane];

    for (int rr = 0; rr < 8; rr++) {
        int r = wid * 8 + rr;
        int row = m0 + r;
        float4 c = ((const float4*)(Cs + r * CPITCH))[lane];
        c.x += bb.x; c.y += bb.y; c.z += bb.z; c.w += bb.w;
        float s = c.x + c.y + c.z + c.w;
#pragma unroll
        for (int o = 16; o > 0; o >>= 1) s += __shfl_xor_sync(0xffffffffu, s, o);
        float mu = s * (1.f / 128.f);
        float dx = c.x - mu, dy = c.y - mu, dz = c.z - mu, dw = c.w - mu;
        float v = dx * dx + dy * dy + dz * dz + dw * dw;
#pragma unroll
        for (int o = 16; o > 0; o >>= 1) v += __shfl_xor_sync(0xffffffffu, v, o);
        float rs = rsqrtf(v * (1.f / 128.f) + 1e-5f);
        if (row < NN) {
            float4 o4;
            o4.x = fmaxf(dx * rs * gg.x + ll.x, 0.f);
            o4.y = fmaxf(dy * rs * gg.y + ll.y, 0.f);
            o4.z = fmaxf(dz * rs * gg.z + ll.z, 0.f);
            o4.w = fmaxf(dw * rs * gg.w + ll.w, 0.f);
            ((float4*)(ob + (size_t)row * DD))[lane] = o4;
        }
    }
}

// ---------------------------------------------------------------
extern "C" void kernel_launch(void* const* d_in, const int* in_sizes, int n_in,
                              void* d_out, int out_size)
{
    const float* x    = (const float*)d_in[0];
    const int*   ei   = (const int*)d_in[1];
    const float* ea   = (const float*)d_in[2];
    const float* bdW1 = (const float*)d_in[3];
    const float* bdb1 = (const float*)d_in[4];
    const float* bdW2 = (const float*)d_in[5];
    const float* bdb2 = (const float*)d_in[6];
    const float* bdW3 = (const float*)d_in[7];
    const float* bdb3 = (const float*)d_in[8];
    const float* etW1 = (const float*)d_in[9];
    const float* etb1 = (const float*)d_in[10];
    const float* etW2 = (const float*)d_in[11];
    const float* etb2 = (const float*)d_in[12];
    const float* bwW1 = (const float*)d_in[13];
    const float* bwb1 = (const float*)d_in[14];
    const float* bwW2 = (const float*)d_in[15];
    const float* bwb2 = (const float*)d_in[16];
    const float* bwW3 = (const float*)d_in[17];
    const float* bwb3 = (const float*)d_in[18];
    const float* nuW  = (const float*)d_in[19];
    const float* nub  = (const float*)d_in[20];
    const float* lng  = (const float*)d_in[21];
    const float* lnb  = (const float*)d_in[22];
    float* out = (float*)d_out;

    // et: A + W1 + W2 (fp16), C aliases W1 region
    const int SMEM_ET = (64 + 128 + 128) * APITCH * 2;              // 87040
    // nu: A + W (fp16) + C (f32) + 3*128 f32
    const int SMEM_NU = (64 + 128) * APITCH * 2 + 64 * CPITCH * 4 + 3 * 128 * 4; // 87552
    cudaFuncSetAttribute((const void*)et_wmma_kernel,
                         cudaFuncAttributeMaxDynamicSharedMemorySize, SMEM_ET);
    cudaFuncSetAttribute((const void*)nu_wmma_kernel,
                         cudaFuncAttributeMaxDynamicSharedMemorySize, SMEM_NU);

    prep_kernel<<<(2 * NN + 255) / 256, 256>>>();
    convw_kernel<<<96, 256>>>(etW1, etW2, nuW);
    et_wmma_kernel<<<dim3(NTILE, 2), 256, SMEM_ET>>>(x, etb1, etb2);
    boundary_kernel<<<dim3((NN + 127) / 128, 2), 128>>>(x, bdW1, bdb1, bdW2, bdb2, bdW3, bdb3);
    hist_kernel<<<dim3((EE + 255) / 256, 2), 256>>>(ei);
    scan1_kernel<<<dim3(NCHUNK, 2), 1024>>>();
    scan2_kernel<<<1, 32>>>();
    scan3_kernel<<<dim3(NCHUNK, 2), 1024>>>();
    bin_kernel<<<dim3((EE + 255) / 256, 2), 256>>>(ei, ea);
    gather_kernel<<<dim3((NN + 7) / 8, 2), 256>>>(x, bwW1, bwb1, bwW2, bwb2, bwW3, bwb3);
    nu_wmma_kernel<<<dim3(NTILE, 2), 256, SMEM_NU>>>(nub, lng, lnb, out);
}

// round 15
// speedup vs baseline: 1.0190x; 1.0190x over previous
#include <cuda_runtime.h>
#include <cuda_fp16.h>
#include <cuda_bf16.h>
#include <mma.h>
#include <math.h>

using namespace nvcuda;

#define NN 50000
#define DD 128
#define EE 800000
#define NCHUNK 49   // ceil(50000/1024)

#define APITCH 136  // half pitch (272B = 17 uint4) for fp16 smem tiles
#define CPITCH 132  // float pitch for C smem tile
#define GTM 64      // gemm M tile (rows per CTA)
#define NTILE 782   // ceil(50000/64)

// -------- device scratch (no runtime allocation allowed) --------
__device__ float  g_b[2 * NN];                 // boundary scores
__device__ __half g_t[2 * (size_t)NN * DD];    // transformed features (fp16)
__device__ __half g_xh[2 * (size_t)NN * DD];   // x in fp16
__device__ __half g_updh[2 * (size_t)NN * DD]; // x + aggregated messages (fp16)
__device__ __half g_etW1h[2 * 128 * 128];
__device__ __half g_etW2h[2 * 128 * 128];
__device__ __half g_nuWh[2 * 128 * 128];
__device__ int    g_cnt[2 * NN];
__device__ int    g_off[2 * NN];
__device__ int    g_cur[2 * NN];
__device__ int    g_bsum[2 * 64];
__device__ int    g_srcA[2 * (size_t)EE];
__device__ float  g_cvalA[2 * (size_t)EE];

// ---------------------------------------------------------------
__global__ void prep_kernel() {
    int i = blockIdx.x * blockDim.x + threadIdx.x;
    if (i < 2 * NN) g_cnt[i] = 0;
}

// weights f32 -> f16 (once)
__global__ void convw_kernel(const float* __restrict__ etW1,
                             const float* __restrict__ etW2,
                             const float* __restrict__ nuW) {
    int i = blockIdx.x * 256 + threadIdx.x;   // each thread: 4 floats
    const int per = 2 * 128 * 128 / 4;        // 8192
    const float* src; __half* dst; int k;
    if (i < per)            { src = etW1; dst = g_etW1h; k = i; }
    else if (i < 2 * per)   { src = etW2; dst = g_etW2h; k = i - per; }
    else if (i < 3 * per)   { src = nuW;  dst = g_nuWh;  k = i - 2 * per; }
    else return;
    float4 v = ((const float4*)src)[k];
    __half2* d = (__half2*)dst + (size_t)k * 2;
    d[0] = __floats2half2_rn(v.x, v.y);
    d[1] = __floats2half2_rn(v.z, v.w);
}

// x f32 -> f16 (once)
__global__ __launch_bounds__(256) void convx_kernel(const float* __restrict__ x) {
    size_t i = (size_t)blockIdx.x * 256 + threadIdx.x;  // 4 floats each
    size_t total = (size_t)2 * NN * DD / 4;
    if (i < total) {
        float4 v = ((const float4*)x)[i];
        __half2* d = (__half2*)g_xh + i * 2;
        d[0] = __floats2half2_rn(v.x, v.y);
        d[1] = __floats2half2_rn(v.z, v.w);
    }
}

__global__ __launch_bounds__(256) void hist_kernel(const int* __restrict__ ei) {
    int type = blockIdx.y;
    int j = blockIdx.x * 256 + threadIdx.x;
    if (j >= EE) return;
    int d = ei[(size_t)type * 2 * EE + EE + j];
    atomicAdd(&g_cnt[type * NN + d], 1);
}

// ---------------------------------------------------------------
// decoupled 3-phase exclusive scan
// ---------------------------------------------------------------
__global__ __launch_bounds__(1024) void scan1_kernel() {
    __shared__ int warpsums[32];
    int type = blockIdx.y, chunk = blockIdx.x;
    int tid = threadIdx.x, lane = tid & 31, wid = tid >> 5;
    int idx = chunk * 1024 + tid;
    int v = (idx < NN) ? g_cnt[type * NN + idx] : 0;
    int inc = v;
#pragma unroll
    for (int o = 1; o < 32; o <<= 1) {
        int y = __shfl_up_sync(0xffffffffu, inc, o);
        if (lane >= o) inc += y;
    }
    if (lane == 31) warpsums[wid] = inc;
    __syncthreads();
    if (tid < 32) {
        int w = warpsums[tid];
        int s = w;
#pragma unroll
        for (int o = 1; o < 32; o <<= 1) {
            int y = __shfl_up_sync(0xffffffffu, s, o);
            if (tid >= o) s += y;
        }
        warpsums[tid] = s - w;
    }
    __syncthreads();
    int excl = inc - v + warpsums[wid];
    if (idx < NN) g_off[type * NN + idx] = excl;
    if (tid == 1023) g_bsum[type * 64 + chunk] = excl + v;
}

__global__ void scan2_kernel() {
    int type = threadIdx.x;
    if (type < 2) {
        int run = 0;
        for (int c = 0; c < NCHUNK; c++) {
            int v = g_bsum[type * 64 + c];
            g_bsum[type * 64 + c] = run;
            run += v;
        }
    }
}

__global__ __launch_bounds__(1024) void scan3_kernel() {
    int type = blockIdx.y, chunk = blockIdx.x;
    int idx = chunk * 1024 + threadIdx.x;
    if (idx < NN) {
        int o = g_off[type * NN + idx] + g_bsum[type * 64 + chunk];
        g_off[type * NN + idx] = o;
        g_cur[type * NN + idx] = o;
    }
}

// ---------------------------------------------------------------
// boundary MLP (fp32; split hidden layer into two 32-wide passes to
// cut regs 138 -> ~85 and double occupancy)
// ---------------------------------------------------------------
__global__ __launch_bounds__(128, 6) void boundary_kernel(
    const float* __restrict__ x,
    const float* __restrict__ bdW1, const float* __restrict__ bdb1,
    const float* __restrict__ bdW2, const float* __restrict__ bdb2,
    const float* __restrict__ bdW3, const float* __restrict__ bdb3)
{
    __shared__ float W1s[128 * 64];
    __shared__ float W2s[64 * 32];
    __shared__ float W3s[32];
    __shared__ float b1s[64], b2s[32];
    __shared__ float b3s;

    int type = blockIdx.y;
    int tid = threadIdx.x;
    const float* W1 = bdW1 + (size_t)type * 128 * 64;
    const float* W2 = bdW2 + (size_t)type * 64 * 32;
    for (int i = tid; i < 128 * 64; i += 128) W1s[i] = W1[i];
    for (int i = tid; i < 64 * 32; i += 128) W2s[i] = W2[i];
    if (tid < 32) W3s[tid] = bdW3[type * 32 + tid];
    if (tid < 64) b1s[tid] = bdb1[type * 64 + tid];
    if (tid < 32) b2s[tid] = bdb2[type * 32 + tid];
    if (tid == 0) b3s = bdb3[type];
    __syncthreads();

    int node = blockIdx.x * 128 + tid;
    if (node >= NN) return;

    const float4* xr = (const float4*)(x + ((size_t)type * NN + node) * DD);

    float h2[32];
#pragma unroll
    for (int j = 0; j < 32; j++) h2[j] = b2s[j];

#pragma unroll 1
    for (int half = 0; half < 2; half++) {
        float h1[32];
#pragma unroll
        for (int j = 0; j < 32; j++) h1[j] = b1s[half * 32 + j];

        for (int d4 = 0; d4 < 32; d4++) {
            float4 xv = xr[d4];          // L1-hit on second pass
            float vs[4] = {xv.x, xv.y, xv.z, xv.w};
#pragma unroll
            for (int dd = 0; dd < 4; dd++) {
                float v = vs[dd];
                const float4* wr = (const float4*)&W1s[(d4 * 4 + dd) * 64 + half * 32];
#pragma unroll
                for (int q = 0; q < 8; q++) {
                    float4 w = wr[q];
                    h1[q * 4 + 0] += v * w.x;
                    h1[q * 4 + 1] += v * w.y;
                    h1[q * 4 + 2] += v * w.z;
                    h1[q * 4 + 3] += v * w.w;
                }
            }
        }
#pragma unroll
        for (int j = 0; j < 32; j++) h1[j] = fmaxf(h1[j], 0.f);

#pragma unroll
        for (int k = 0; k < 32; k++) {
            float v = h1[k];
            const float4* wr = (const float4*)&W2s[(half * 32 + k) * 32];
#pragma unroll
            for (int q = 0; q < 8; q++) {
                float4 w = wr[q];
                h2[q * 4 + 0] += v * w.x;
                h2[q * 4 + 1] += v * w.y;
                h2[q * 4 + 2] += v * w.z;
                h2[q * 4 + 3] += v * w.w;
            }
        }
    }

    float z = b3s;
#pragma unroll
    for (int k = 0; k < 32; k++) z += fmaxf(h2[k], 0.f) * W3s[k];

    g_b[type * NN + node] = 1.f / (1.f + expf(-z));
}

// ---------------------------------------------------------------
// wmma gemm: C(64x128) = A(64x128) @ B(128x128), immediate store
// 8 warps: wm = wid&3 (16 rows each), wn = wid>>2 (64 cols each)
// ---------------------------------------------------------------
__device__ __forceinline__ void wmma_tile64(
    const __half* Ah, const __half* Bh, float* Cs, int wid)
{
    int wm = wid & 3, wn = wid >> 2;
    wmma::fragment<wmma::accumulator, 16, 16, 16, float> acc[4];
#pragma unroll
    for (int j = 0; j < 4; j++) wmma::fill_fragment(acc[j], 0.f);

#pragma unroll
    for (int k = 0; k < 8; k++) {
        wmma::fragment<wmma::matrix_a, 16, 16, 16, __half, wmma::row_major> a;
        wmma::fragment<wmma::matrix_b, 16, 16, 16, __half, wmma::row_major> b[4];
        wmma::load_matrix_sync(a, Ah + (wm * 16) * APITCH + k * 16, APITCH);
#pragma unroll
        for (int j = 0; j < 4; j++)
            wmma::load_matrix_sync(b[j], Bh + (k * 16) * APITCH + wn * 64 + j * 16, APITCH);
#pragma unroll
        for (int j = 0; j < 4; j++)
            wmma::mma_sync(acc[j], a, b[j], acc[j]);
    }
#pragma unroll
    for (int j = 0; j < 4; j++)
        wmma::store_matrix_sync(Cs + (wm * 16) * CPITCH + wn * 64 + j * 16,
                                acc[j], CPITCH, wmma::mem_row_major);
}

// fp16 tile loaders: pure uint4 copies (no conversion)
__device__ __forceinline__ void copy_rows_h16(
    __half* dst, const __half* src, int row0, int rowlim, int tid)
{
    uint4* d = (uint4*)dst;
    const uint4* s = (const uint4*)src;
    for (int i = tid; i < 64 * 16; i += 256) {
        int r = i >> 4, c = i & 15;
        int row = row0 + r;
        uint4 v = make_uint4(0u, 0u, 0u, 0u);
        if (row < rowlim) v = s[(size_t)row * 16 + c];
        d[r * 17 + c] = v;                    // APITCH = 136 halves = 17 uint4
    }
}

__device__ __forceinline__ void copy_w_h16(
    __half* dst, const __half* src, int tid)
{
    uint4* d = (uint4*)dst;
    const uint4* s = (const uint4*)src;
    for (int i = tid; i < 128 * 16; i += 256) {
        int r = i >> 4, c = i & 15;
        d[r * 17 + c] = s[r * 16 + c];
    }
}

// ---------------------------------------------------------------
// et (tensor core): t = relu(x @ W1 + b1) @ W2 + b2  -> g_t (fp16)
// both weight tiles resident; Cs aliases B1h (dead after mma1)
// ---------------------------------------------------------------
__global__ __launch_bounds__(256, 2) void et_wmma_kernel(
    const float* __restrict__ b1g, const float* __restrict__ b2g)
{
    extern __shared__ char smem_raw[];
    __half* Ah  = (__half*)smem_raw;           // 64*APITCH
    __half* B1h = Ah + 64 * APITCH;            // 128*APITCH
    __half* B2h = B1h + 128 * APITCH;          // 128*APITCH
    float*  Cs  = (float*)B1h;                 // alias (33792B <= 34816B)

    int type = blockIdx.y;
    int m0 = blockIdx.x * GTM;
    int tid = threadIdx.x;
    int wid = tid >> 5;
    int wm = wid & 3, wn = wid >> 2;

    copy_rows_h16(Ah, g_xh + (size_t)type * NN * DD, m0, NN, tid);
    copy_w_h16(B1h, g_etW1h + type * 128 * 128, tid);
    copy_w_h16(B2h, g_etW2h + type * 128 * 128, tid);
    __syncthreads();

    // mma1: compute into register fragments, delay store until all B1 reads done
    wmma::fragment<wmma::accumulator, 16, 16, 16, float> acc[4];
#pragma unroll
    for (int j = 0; j < 4; j++) wmma::fill_fragment(acc[j], 0.f);
#pragma unroll
    for (int k = 0; k < 8; k++) {
        wmma::fragment<wmma::matrix_a, 16, 16, 16, __half, wmma::row_major> a;
        wmma::fragment<wmma::matrix_b, 16, 16, 16, __half, wmma::row_major> b[4];
        wmma::load_matrix_sync(a, Ah + (wm * 16) * APITCH + k * 16, APITCH);
#pragma unroll
        for (int j = 0; j < 4; j++)
            wmma::load_matrix_sync(b[j], B1h + (k * 16) * APITCH + wn * 64 + j * 16, APITCH);
#pragma unroll
        for (int j = 0; j < 4; j++)
            wmma::mma_sync(acc[j], a, b[j], acc[j]);
    }
    __syncthreads();   // all warps done reading B1h
#pragma unroll
    for (int j = 0; j < 4; j++)
        wmma::store_matrix_sync(Cs + (wm * 16) * CPITCH + wn * 64 + j * 16,
                                acc[j], CPITCH, wmma::mem_row_major);
    __syncthreads();

    // bias + relu -> Ah (fp16)
    const float* b1 = b1g + type * 128;
    for (int idx = tid; idx < 64 * 64; idx += 256) {
        int r = idx >> 6, c2 = (idx & 63) * 2;
        float z0 = Cs[r * CPITCH + c2]     + b1[c2];
        float z1 = Cs[r * CPITCH + c2 + 1] + b1[c2 + 1];
        *(__half2*)&Ah[r * APITCH + c2] = __floats2half2_rn(fmaxf(z0, 0.f), fmaxf(z1, 0.f));
    }
    __syncthreads();

    // mma2: B2h reads, store to Cs (aliases B1h only — safe)
    wmma_tile64(Ah, B2h, Cs, wid);
    __syncthreads();

    const float* b2 = b2g + type * 128;
    __half2* tb = (__half2*)(g_t + (size_t)type * NN * DD);
    for (int idx = tid; idx < 64 * 64; idx += 256) {
        int r = idx >> 6, c2idx = idx & 63;
        int row = m0 + r;
        if (row < NN) {
            int c2 = c2idx * 2;
            float z0 = Cs[r * CPITCH + c2]     + b2[c2];
            float z1 = Cs[r * CPITCH + c2 + 1] + b2[c2 + 1];
            tb[(size_t)row * 64 + c2idx] = __floats2half2_rn(z0, z1);
        }
    }
}

// ---------------------------------------------------------------
// per-edge coefficient MLP + CSR binning (fused, fp32)
// ---------------------------------------------------------------
__global__ __launch_bounds__(256) void coef_order_kernel(
    const int* __restrict__ ei, const float* __restrict__ ea,
    const float* __restrict__ bwW1, const float* __restrict__ bwb1,
    const float* __restrict__ bwW2, const float* __restrict__ bwb2,
    const float* __restrict__ bwW3, const float* __restrict__ bwb3)
{
    __shared__ float W1s[64], B1s[32], W2s[512], B2s[16], W3s[16];
    __shared__ float B3s;
    int type = blockIdx.y;
    int tid = threadIdx.x;
    if (tid < 64) W1s[tid] = bwW1[type * 64 + tid];
    if (tid < 32) B1s[tid] = bwb1[type * 32 + tid];
    for (int i = tid; i < 512; i += 256) W2s[i] = bwW2[type * 512 + i];
    if (tid < 16) B2s[tid] = bwb2[type * 16 + tid];
    if (tid < 16) W3s[tid] = bwW3[type * 16 + tid];
    if (tid == 0) B3s = bwb3[type];
    __syncthreads();

    int j = blockIdx.x * 256 + tid;
    if (j >= EE) return;
    const int* eib = ei + (size_t)type * 2 * EE;
    int s = eib[j];
    int d = eib[EE + j];
    float sb = g_b[type * NN + s];
    float db = g_b[(1 - type) * NN + d];

    float h1[32];
#pragma unroll
    for (int q = 0; q < 32; q++)
        h1[q] = fmaxf(sb * W1s[q] + db * W1s[32 + q] + B1s[q], 0.f);

    float4 h2v[4];
#pragma unroll
    for (int p = 0; p < 4; p++) h2v[p] = ((const float4*)B2s)[p];
    const float4* W2v = (const float4*)W2s;
#pragma unroll
    for (int q = 0; q < 32; q++) {
        float v = h1[q];
#pragma unroll
        for (int p = 0; p < 4; p++) {
            float4 w = W2v[q * 4 + p];
            h2v[p].x += v * w.x;
            h2v[p].y += v * w.y;
            h2v[p].z += v * w.z;
            h2v[p].w += v * w.w;
        }
    }
    float z = B3s;
#pragma unroll
    for (int p = 0; p < 4; p++) {
        z += fmaxf(h2v[p].x, 0.f) * W3s[p * 4 + 0];
        z += fmaxf(h2v[p].y, 0.f) * W3s[p * 4 + 1];
        z += fmaxf(h2v[p].z, 0.f) * W3s[p * 4 + 2];
        z += fmaxf(h2v[p].w, 0.f) * W3s[p * 4 + 3];
    }

    float w = 1.f / (1.f + expf(-z));
    if (sb > 0.3f || db > 0.3f) w *= 2.f;
    float c = ea[(size_t)type * EE + j] * w;

    int pos = atomicAdd(&g_cur[type * NN + d], 1);
    g_srcA[(size_t)type * EE + pos] = s;
    g_cvalA[(size_t)type * EE + pos] = c;
}

// ---------------------------------------------------------------
// gather: updh[to][n] = fp16(x[to][n] + sum over CSR(e=1-to, dst n))
// ---------------------------------------------------------------
__global__ __launch_bounds__(256) void gather_kernel(const float* __restrict__ x)
{
    int to = blockIdx.y;
    int e = 1 - to;
    int lane = threadIdx.x & 31;
    int warp = threadIdx.x >> 5;
    int n = blockIdx.x * 8 + warp;
    if (n >= NN) return;

    int base = e * NN + n;
    int st = g_off[base];
    int en = g_cur[base];

    const uint2* tb = (const uint2*)(g_t + (size_t)e * NN * DD);
    const int* srcp = g_srcA + (size_t)e * EE;
    const float* cvp = g_cvalA + (size_t)e * EE;

    float4 acc = ((const float4*)(x + ((size_t)to * NN + n) * DD))[lane];

    int i = st;
    for (; i + 3 < en; i += 4) {
        int s0 = __ldg(srcp + i),     s1 = __ldg(srcp + i + 1);
        int s2 = __ldg(srcp + i + 2), s3 = __ldg(srcp + i + 3);
        float c0 = __ldg(cvp + i),     c1 = __ldg(cvp + i + 1);
        float c2 = __ldg(cvp + i + 2), c3 = __ldg(cvp + i + 3);
        uint2 h0 = tb[(size_t)s0 * 32 + lane];
        uint2 h1 = tb[(size_t)s1 * 32 + lane];
        uint2 h2 = tb[(size_t)s2 * 32 + lane];
        uint2 h3 = tb[(size_t)s3 * 32 + lane];
        float2 a0 = __half22float2(*(__half2*)&h0.x), b0 = __half22float2(*(__half2*)&h0.y);
        float2 a1 = __half22float2(*(__half2*)&h1.x), b1 = __half22float2(*(__half2*)&h1.y);
        float2 a2 = __half22float2(*(__half2*)&h2.x), b2 = __half22float2(*(__half2*)&h2.y);
        float2 a3 = __half22float2(*(__half2*)&h3.x), b3 = __half22float2(*(__half2*)&h3.y);
        acc.x += a0.x * c0; acc.y += a0.y * c0; acc.z += b0.x * c0; acc.w += b0.y * c0;
        acc.x += a1.x * c1; acc.y += a1.y * c1; acc.z += b1.x * c1; acc.w += b1.y * c1;
        acc.x += a2.x * c2; acc.y += a2.y * c2; acc.z += b2.x * c2; acc.w += b2.y * c2;
        acc.x += a3.x * c3; acc.y += a3.y * c3; acc.z += b3.x * c3; acc.w += b3.y * c3;
    }
    for (; i < en; i++) {
        int s0 = __ldg(srcp + i);
        float c0 = __ldg(cvp + i);
        uint2 h0 = tb[(size_t)s0 * 32 + lane];
        float2 a0 = __half22float2(*(__half2*)&h0.x), b0 = __half22float2(*(__half2*)&h0.y);
        acc.x += a0.x * c0; acc.y += a0.y * c0; acc.z += b0.x * c0; acc.w += b0.y * c0;
    }

    __half2 p0 = __floats2half2_rn(acc.x, acc.y);
    __half2 p1 = __floats2half2_rn(acc.z, acc.w);
    uint2 u;
    u.x = *(unsigned*)&p0;
    u.y = *(unsigned*)&p1;
    ((uint2*)(g_updh + ((size_t)to * NN + n) * DD))[lane] = u;
}

// ---------------------------------------------------------------
// nu (tensor core): out = relu(LN(updh @ nuW + nub) * g + b)
// ---------------------------------------------------------------
__global__ __launch_bounds__(256, 2) void nu_wmma_kernel(
    const float* __restrict__ nub,
    const float* __restrict__ lng, const float* __restrict__ lnb,
    float* __restrict__ out)
{
    extern __shared__ char smem_raw[];
    __half* Ah = (__half*)smem_raw;
    __half* Bh = Ah + 64 * APITCH;
    float*  Cs = (float*)(Bh + 128 * APITCH);
    float*  nubS = Cs + 64 * CPITCH;    // 128
    float*  gS   = nubS + 128;          // 128
    float*  lbS  = gS + 128;            // 128

    int type = blockIdx.y;
    int m0 = blockIdx.x * GTM;
    int tid = threadIdx.x;
    int wid = tid >> 5;
    int lane = tid & 31;

    copy_rows_h16(Ah, g_updh + (size_t)type * NN * DD, m0, NN, tid);
    copy_w_h16(Bh, g_nuWh + type * 128 * 128, tid);
    if (tid < 128) {
        nubS[tid] = nub[type * 128 + tid];
        gS[tid]   = lng[type * 128 + tid];
        lbS[tid]  = lnb[type * 128 + tid];
    }
    __syncthreads();

    wmma_tile64(Ah, Bh, Cs, wid);
    __syncthreads();

    // LN + relu epilogue: warp per 8 rows, lane owns 4 columns
    float* ob = out + (size_t)type * NN * DD;
    float4 bb = ((const float4*)nubS)[lane];
    float4 gg = ((const float4*)gS)[lane];
    float4 ll = ((const float4*)lbS)[lane];

    for (int rr = 0; rr < 8; rr++) {
        int r = wid * 8 + rr;
        int row = m0 + r;
        float4 c = ((const float4*)(Cs + r * CPITCH))[lane];
        c.x += bb.x; c.y += bb.y; c.z += bb.z; c.w += bb.w;
        float s = c.x + c.y + c.z + c.w;
#pragma unroll
        for (int o = 16; o > 0; o >>= 1) s += __shfl_xor_sync(0xffffffffu, s, o);
        float mu = s * (1.f / 128.f);
        float dx = c.x - mu, dy = c.y - mu, dz = c.z - mu, dw = c.w - mu;
        float v = dx * dx + dy * dy + dz * dz + dw * dw;
#pragma unroll
        for (int o = 16; o > 0; o >>= 1) v += __shfl_xor_sync(0xffffffffu, v, o);
        float rs = rsqrtf(v * (1.f / 128.f) + 1e-5f);
        if (row < NN) {
            float4 o4;
            o4.x = fmaxf(dx * rs * gg.x + ll.x, 0.f);
            o4.y = fmaxf(dy * rs * gg.y + ll.y, 0.f);
            o4.z = fmaxf(dz * rs * gg.z + ll.z, 0.f);
            o4.w = fmaxf(dw * rs * gg.w + ll.w, 0.f);
            ((float4*)(ob + (size_t)row * DD))[lane] = o4;
        }
    }
}

// ---------------------------------------------------------------
extern "C" void kernel_launch(void* const* d_in, const int* in_sizes, int n_in,
                              void* d_out, int out_size)
{
    const float* x    = (const float*)d_in[0];
    const int*   ei   = (const int*)d_in[1];
    const float* ea   = (const float*)d_in[2];
    const float* bdW1 = (const float*)d_in[3];
    const float* bdb1 = (const float*)d_in[4];
    const float* bdW2 = (const float*)d_in[5];
    const float* bdb2 = (const float*)d_in[6];
    const float* bdW3 = (const float*)d_in[7];
    const float* bdb3 = (const float*)d_in[8];
    const float* etW1 = (const float*)d_in[9];
    const float* etb1 = (const float*)d_in[10];
    const float* etW2 = (const float*)d_in[11];
    const float* etb2 = (const float*)d_in[12];
    const float* bwW1 = (const float*)d_in[13];
    const float* bwb1 = (const float*)d_in[14];
    const float* bwW2 = (const float*)d_in[15];
    const float* bwb2 = (const float*)d_in[16];
    const float* bwW3 = (const float*)d_in[17];
    const float* bwb3 = (const float*)d_in[18];
    const float* nuW  = (const float*)d_in[19];
    const float* nub  = (const float*)d_in[20];
    const float* lng  = (const float*)d_in[21];
    const float* lnb  = (const float*)d_in[22];
    float* out = (float*)d_out;

    // et: A + W1 + W2 (fp16), C aliases W1 region
    const int SMEM_ET = (64 + 128 + 128) * APITCH * 2;              // 87040
    // nu: A + W (fp16) + C (f32) + 3*128 f32
    const int SMEM_NU = (64 + 128) * APITCH * 2 + 64 * CPITCH * 4 + 3 * 128 * 4; // 87552
    cudaFuncSetAttribute((const void*)et_wmma_kernel,
                         cudaFuncAttributeMaxDynamicSharedMemorySize, SMEM_ET);
    cudaFuncSetAttribute((const void*)nu_wmma_kernel,
                         cudaFuncAttributeMaxDynamicSharedMemorySize, SMEM_NU);

    prep_kernel<<<(2 * NN + 255) / 256, 256>>>();
    convw_kernel<<<96, 256>>>(etW1, etW2, nuW);
    convx_kernel<<<(2 * NN * DD / 4 + 255) / 256, 256>>>(x);
    boundary_kernel<<<dim3((NN + 127) / 128, 2), 128>>>(x, bdW1, bdb1, bdW2, bdb2, bdW3, bdb3);
    et_wmma_kernel<<<dim3(NTILE, 2), 256, SMEM_ET>>>(etb1, etb2);
    hist_kernel<<<dim3((EE + 255) / 256, 2), 256>>>(ei);
    scan1_kernel<<<dim3(NCHUNK, 2), 1024>>>();
    scan2_kernel<<<1, 32>>>();
    scan3_kernel<<<dim3(NCHUNK, 2), 1024>>>();
    coef_order_kernel<<<dim3((EE + 255) / 256, 2), 256>>>(ei, ea, bwW1, bwb1, bwW2, bwb2, bwW3, bwb3);
    gather_kernel<<<dim3((NN + 7) / 8, 2), 256>>>(x);
    nu_wmma_kernel<<<dim3(NTILE, 2), 256, SMEM_NU>>>(nub, lng, lnb, out);
}

// round 17
// speedup vs baseline: 1.1215x; 1.1006x over previous
#include <cuda_runtime.h>
#include <cuda_fp16.h>
#include <cuda_bf16.h>
#include <mma.h>
#include <math.h>

using namespace nvcuda;

#define NN 50000
#define DD 128
#define EE 800000
#define NCHUNK 49   // ceil(50000/1024)

#define APITCH 136  // half pitch (272B = 17 uint4) for fp16 smem tiles
#define CPITCH 132  // float pitch for C smem tile
#define GTM 64      // gemm M tile (rows per CTA)
#define NTILE 782   // ceil(50000/64)

// -------- device scratch (no runtime allocation allowed) --------
__device__ float  g_b[2 * NN];                 // boundary scores
__device__ __half g_t[2 * (size_t)NN * DD];    // transformed features (fp16)
__device__ __half g_xh[2 * (size_t)NN * DD];   // x in fp16
__device__ __half g_updh[2 * (size_t)NN * DD]; // x + aggregated messages (fp16)
__device__ __half g_etW1h[2 * 128 * 128];
__device__ __half g_etW2h[2 * 128 * 128];
__device__ __half g_nuWh[2 * 128 * 128];
__device__ int    g_cnt[2 * NN];
__device__ int    g_off[2 * NN];
__device__ int    g_cur[2 * NN];
__device__ int    g_bsum[2 * 64];
__device__ int    g_srcA[2 * (size_t)EE];
__device__ float  g_cvalA[2 * (size_t)EE];

// ---------------------------------------------------------------
__global__ void prep_kernel() {
    int i = blockIdx.x * blockDim.x + threadIdx.x;
    if (i < 2 * NN) g_cnt[i] = 0;
}

// weights f32 -> f16 (once)
__global__ void convw_kernel(const float* __restrict__ etW1,
                             const float* __restrict__ etW2,
                             const float* __restrict__ nuW) {
    int i = blockIdx.x * 256 + threadIdx.x;   // each thread: 4 floats
    const int per = 2 * 128 * 128 / 4;        // 8192
    const float* src; __half* dst; int k;
    if (i < per)            { src = etW1; dst = g_etW1h; k = i; }
    else if (i < 2 * per)   { src = etW2; dst = g_etW2h; k = i - per; }
    else if (i < 3 * per)   { src = nuW;  dst = g_nuWh;  k = i - 2 * per; }
    else return;
    float4 v = ((const float4*)src)[k];
    __half2* d = (__half2*)dst + (size_t)k * 2;
    d[0] = __floats2half2_rn(v.x, v.y);
    d[1] = __floats2half2_rn(v.z, v.w);
}

// x f32 -> f16 (once)
__global__ __launch_bounds__(256) void convx_kernel(const float* __restrict__ x) {
    size_t i = (size_t)blockIdx.x * 256 + threadIdx.x;  // 4 floats each
    size_t total = (size_t)2 * NN * DD / 4;
    if (i < total) {
        float4 v = ((const float4*)x)[i];
        __half2* d = (__half2*)g_xh + i * 2;
        d[0] = __floats2half2_rn(v.x, v.y);
        d[1] = __floats2half2_rn(v.z, v.w);
    }
}

__global__ __launch_bounds__(256) void hist_kernel(const int* __restrict__ ei) {
    int type = blockIdx.y;
    int j = blockIdx.x * 256 + threadIdx.x;
    if (j >= EE) return;
    int d = ei[(size_t)type * 2 * EE + EE + j];
    atomicAdd(&g_cnt[type * NN + d], 1);
}

// ---------------------------------------------------------------
// decoupled 3-phase exclusive scan
// ---------------------------------------------------------------
__global__ __launch_bounds__(1024) void scan1_kernel() {
    __shared__ int warpsums[32];
    int type = blockIdx.y, chunk = blockIdx.x;
    int tid = threadIdx.x, lane = tid & 31, wid = tid >> 5;
    int idx = chunk * 1024 + tid;
    int v = (idx < NN) ? g_cnt[type * NN + idx] : 0;
    int inc = v;
#pragma unroll
    for (int o = 1; o < 32; o <<= 1) {
        int y = __shfl_up_sync(0xffffffffu, inc, o);
        if (lane >= o) inc += y;
    }
    if (lane == 31) warpsums[wid] = inc;
    __syncthreads();
    if (tid < 32) {
        int w = warpsums[tid];
        int s = w;
#pragma unroll
        for (int o = 1; o < 32; o <<= 1) {
            int y = __shfl_up_sync(0xffffffffu, s, o);
            if (tid >= o) s += y;
        }
        warpsums[tid] = s - w;
    }
    __syncthreads();
    int excl = inc - v + warpsums[wid];
    if (idx < NN) g_off[type * NN + idx] = excl;
    if (tid == 1023) g_bsum[type * 64 + chunk] = excl + v;
}

__global__ void scan2_kernel() {
    int type = threadIdx.x;
    if (type < 2) {
        int run = 0;
        for (int c = 0; c < NCHUNK; c++) {
            int v = g_bsum[type * 64 + c];
            g_bsum[type * 64 + c] = run;
            run += v;
        }
    }
}

__global__ __launch_bounds__(1024) void scan3_kernel() {
    int type = blockIdx.y, chunk = blockIdx.x;
    int idx = chunk * 1024 + threadIdx.x;
    if (idx < NN) {
        int o = g_off[type * NN + idx] + g_bsum[type * 64 + chunk];
        g_off[type * NN + idx] = o;
        g_cur[type * NN + idx] = o;
    }
}

// ---------------------------------------------------------------
// boundary MLP (fp32): 2 threads per node (part = tid&1).
// Each thread: h1 for 32 hidden units (full ILP), shfl-exchange for
// layer 2, shfl-combine for layer 3. 256 thr / 128 nodes per CTA.
// ---------------------------------------------------------------
__global__ __launch_bounds__(256) void boundary_kernel(
    const float* __restrict__ x,
    const float* __restrict__ bdW1, const float* __restrict__ bdb1,
    const float* __restrict__ bdW2, const float* __restrict__ bdb2,
    const float* __restrict__ bdW3, const float* __restrict__ bdb3)
{
    __shared__ float W1s[128 * 64];
    __shared__ float W2s[64 * 32];
    __shared__ float W3s[32];
    __shared__ float b1s[64], b2s[32];
    __shared__ float b3s;

    int type = blockIdx.y;
    int tid = threadIdx.x;
    const float* W1 = bdW1 + (size_t)type * 128 * 64;
    const float* W2 = bdW2 + (size_t)type * 64 * 32;
    for (int i = tid; i < 128 * 64; i += 256) W1s[i] = W1[i];
    for (int i = tid; i < 64 * 32; i += 256) W2s[i] = W2[i];
    if (tid < 32) W3s[tid] = bdW3[type * 32 + tid];
    if (tid < 64) b1s[tid] = bdb1[type * 64 + tid];
    if (tid < 32) b2s[tid] = bdb2[type * 32 + tid];
    if (tid == 0) b3s = bdb3[type];
    __syncthreads();

    int node = blockIdx.x * 128 + (tid >> 1);
    int part = tid & 1;
    bool valid = node < NN;
    int nclamp = valid ? node : (NN - 1);

    const float4* xr = (const float4*)(x + ((size_t)type * NN + nclamp) * DD);

    // layer 1: this thread's 32 hidden units [part*32, part*32+32)
    float h1[32];
#pragma unroll
    for (int j = 0; j < 32; j++) h1[j] = b1s[part * 32 + j];

    for (int d4 = 0; d4 < 32; d4++) {
        float4 xv = xr[d4];
        float vs[4] = {xv.x, xv.y, xv.z, xv.w};
#pragma unroll
        for (int dd = 0; dd < 4; dd++) {
            float v = vs[dd];
            const float4* wr = (const float4*)&W1s[(d4 * 4 + dd) * 64 + part * 32];
#pragma unroll
            for (int q = 0; q < 8; q++) {
                float4 w = wr[q];
                h1[q * 4 + 0] += v * w.x;
                h1[q * 4 + 1] += v * w.y;
                h1[q * 4 + 2] += v * w.z;
                h1[q * 4 + 3] += v * w.w;
            }
        }
    }
#pragma unroll
    for (int j = 0; j < 32; j++) h1[j] = fmaxf(h1[j], 0.f);

    // layer 2: this thread's 16 outputs [part*16, part*16+16)
    float h2[16];
#pragma unroll
    for (int p = 0; p < 16; p++) h2[p] = b2s[part * 16 + p];

#pragma unroll
    for (int k = 0; k < 32; k++) {
        float vo = h1[k];                                    // h1[part*32+k]
        float vp = __shfl_xor_sync(0xffffffffu, vo, 1);      // h1[(1-part)*32+k]
        const float4* wo = (const float4*)&W2s[(part * 32 + k) * 32 + part * 16];
        const float4* wp = (const float4*)&W2s[((1 - part) * 32 + k) * 32 + part * 16];
#pragma unroll
        for (int q = 0; q < 4; q++) {
            float4 a = wo[q];
            float4 b = wp[q];
            h2[q * 4 + 0] += vo * a.x + vp * b.x;
            h2[q * 4 + 1] += vo * a.y + vp * b.y;
            h2[q * 4 + 2] += vo * a.z + vp * b.z;
            h2[q * 4 + 3] += vo * a.w + vp * b.w;
        }
    }

    // layer 3: partial over own 16, combine with partner
    float zp = 0.f;
#pragma unroll
    for (int p = 0; p < 16; p++)
        zp += fmaxf(h2[p], 0.f) * W3s[part * 16 + p];
    float z = zp + __shfl_xor_sync(0xffffffffu, zp, 1) + b3s;

    if (valid && part == 0)
        g_b[type * NN + node] = 1.f / (1.f + expf(-z));
}

// ---------------------------------------------------------------
// wmma gemm: C(64x128) = A(64x128) @ B(128x128), immediate store
// 8 warps: wm = wid&3 (16 rows each), wn = wid>>2 (64 cols each)
// ---------------------------------------------------------------
__device__ __forceinline__ void wmma_tile64(
    const __half* Ah, const __half* Bh, float* Cs, int wid)
{
    int wm = wid & 3, wn = wid >> 2;
    wmma::fragment<wmma::accumulator, 16, 16, 16, float> acc[4];
#pragma unroll
    for (int j = 0; j < 4; j++) wmma::fill_fragment(acc[j], 0.f);

#pragma unroll
    for (int k = 0; k < 8; k++) {
        wmma::fragment<wmma::matrix_a, 16, 16, 16, __half, wmma::row_major> a;
        wmma::fragment<wmma::matrix_b, 16, 16, 16, __half, wmma::row_major> b[4];
        wmma::load_matrix_sync(a, Ah + (wm * 16) * APITCH + k * 16, APITCH);
#pragma unroll
        for (int j = 0; j < 4; j++)
            wmma::load_matrix_sync(b[j], Bh + (k * 16) * APITCH + wn * 64 + j * 16, APITCH);
#pragma unroll
        for (int j = 0; j < 4; j++)
            wmma::mma_sync(acc[j], a, b[j], acc[j]);
    }
#pragma unroll
    for (int j = 0; j < 4; j++)
        wmma::store_matrix_sync(Cs + (wm * 16) * CPITCH + wn * 64 + j * 16,
                                acc[j], CPITCH, wmma::mem_row_major);
}

// fp16 tile loaders: pure uint4 copies (no conversion)
__device__ __forceinline__ void copy_rows_h16(
    __half* dst, const __half* src, int row0, int rowlim, int tid)
{
    uint4* d = (uint4*)dst;
    const uint4* s = (const uint4*)src;
    for (int i = tid; i < 64 * 16; i += 256) {
        int r = i >> 4, c = i & 15;
        int row = row0 + r;
        uint4 v = make_uint4(0u, 0u, 0u, 0u);
        if (row < rowlim) v = s[(size_t)row * 16 + c];
        d[r * 17 + c] = v;                    // APITCH = 136 halves = 17 uint4
    }
}

__device__ __forceinline__ void copy_w_h16(
    __half* dst, const __half* src, int tid)
{
    uint4* d = (uint4*)dst;
    const uint4* s = (const uint4*)src;
    for (int i = tid; i < 128 * 16; i += 256) {
        int r = i >> 4, c = i & 15;
        d[r * 17 + c] = s[r * 16 + c];
    }
}

// ---------------------------------------------------------------
// et (tensor core): t = relu(x @ W1 + b1) @ W2 + b2  -> g_t (fp16)
// both weight tiles resident; Cs aliases B1h (dead after mma1)
// ---------------------------------------------------------------
__global__ __launch_bounds__(256, 2) void et_wmma_kernel(
    const float* __restrict__ b1g, const float* __restrict__ b2g)
{
    extern __shared__ char smem_raw[];
    __half* Ah  = (__half*)smem_raw;           // 64*APITCH
    __half* B1h = Ah + 64 * APITCH;            // 128*APITCH
    __half* B2h = B1h + 128 * APITCH;          // 128*APITCH
    float*  Cs  = (float*)B1h;                 // alias (33792B <= 34816B)

    int type = blockIdx.y;
    int m0 = blockIdx.x * GTM;
    int tid = threadIdx.x;
    int wid = tid >> 5;
    int wm = wid & 3, wn = wid >> 2;

    copy_rows_h16(Ah, g_xh + (size_t)type * NN * DD, m0, NN, tid);
    copy_w_h16(B1h, g_etW1h + type * 128 * 128, tid);
    copy_w_h16(B2h, g_etW2h + type * 128 * 128, tid);
    __syncthreads();

    // mma1: compute into register fragments, delay store until all B1 reads done
    wmma::fragment<wmma::accumulator, 16, 16, 16, float> acc[4];
#pragma unroll
    for (int j = 0; j < 4; j++) wmma::fill_fragment(acc[j], 0.f);
#pragma unroll
    for (int k = 0; k < 8; k++) {
        wmma::fragment<wmma::matrix_a, 16, 16, 16, __half, wmma::row_major> a;
        wmma::fragment<wmma::matrix_b, 16, 16, 16, __half, wmma::row_major> b[4];
        wmma::load_matrix_sync(a, Ah + (wm * 16) * APITCH + k * 16, APITCH);
#pragma unroll
        for (int j = 0; j < 4; j++)
            wmma::load_matrix_sync(b[j], B1h + (k * 16) * APITCH + wn * 64 + j * 16, APITCH);
#pragma unroll
        for (int j = 0; j < 4; j++)
            wmma::mma_sync(acc[j], a, b[j], acc[j]);
    }
    __syncthreads();   // all warps done reading B1h
#pragma unroll
    for (int j = 0; j < 4; j++)
        wmma::store_matrix_sync(Cs + (wm * 16) * CPITCH + wn * 64 + j * 16,
                                acc[j], CPITCH, wmma::mem_row_major);
    __syncthreads();

    // bias + relu -> Ah (fp16)
    const float* b1 = b1g + type * 128;
    for (int idx = tid; idx < 64 * 64; idx += 256) {
        int r = idx >> 6, c2 = (idx & 63) * 2;
        float z0 = Cs[r * CPITCH + c2]     + b1[c2];
        float z1 = Cs[r * CPITCH + c2 + 1] + b1[c2 + 1];
        *(__half2*)&Ah[r * APITCH + c2] = __floats2half2_rn(fmaxf(z0, 0.f), fmaxf(z1, 0.f));
    }
    __syncthreads();

    // mma2: B2h reads, store to Cs (aliases B1h only — safe)
    wmma_tile64(Ah, B2h, Cs, wid);
    __syncthreads();

    const float* b2 = b2g + type * 128;
    __half2* tb = (__half2*)(g_t + (size_t)type * NN * DD);
    for (int idx = tid; idx < 64 * 64; idx += 256) {
        int r = idx >> 6, c2idx = idx & 63;
        int row = m0 + r;
        if (row < NN) {
            int c2 = c2idx * 2;
            float z0 = Cs[r * CPITCH + c2]     + b2[c2];
            float z1 = Cs[r * CPITCH + c2 + 1] + b2[c2 + 1];
            tb[(size_t)row * 64 + c2idx] = __floats2half2_rn(z0, z1);
        }
    }
}

// ---------------------------------------------------------------
// per-edge coefficient MLP + CSR binning (fused, fp32)
// ---------------------------------------------------------------
__global__ __launch_bounds__(256) void coef_order_kernel(
    const int* __restrict__ ei, const float* __restrict__ ea,
    const float* __restrict__ bwW1, const float* __restrict__ bwb1,
    const float* __restrict__ bwW2, const float* __restrict__ bwb2,
    const float* __restrict__ bwW3, const float* __restrict__ bwb3)
{
    __shared__ float W1s[64], B1s[32], W2s[512], B2s[16], W3s[16];
    __shared__ float B3s;
    int type = blockIdx.y;
    int tid = threadIdx.x;
    if (tid < 64) W1s[tid] = bwW1[type * 64 + tid];
    if (tid < 32) B1s[tid] = bwb1[type * 32 + tid];
    for (int i = tid; i < 512; i += 256) W2s[i] = bwW2[type * 512 + i];
    if (tid < 16) B2s[tid] = bwb2[type * 16 + tid];
    if (tid < 16) W3s[tid] = bwW3[type * 16 + tid];
    if (tid == 0) B3s = bwb3[type];
    __syncthreads();

    int j = blockIdx.x * 256 + tid;
    if (j >= EE) return;
    const int* eib = ei + (size_t)type * 2 * EE;
    int s = eib[j];
    int d = eib[EE + j];
    float sb = g_b[type * NN + s];
    float db = g_b[(1 - type) * NN + d];

    float h1[32];
#pragma unroll
    for (int q = 0; q < 32; q++)
        h1[q] = fmaxf(sb * W1s[q] + db * W1s[32 + q] + B1s[q], 0.f);

    float4 h2v[4];
#pragma unroll
    for (int p = 0; p < 4; p++) h2v[p] = ((const float4*)B2s)[p];
    const float4* W2v = (const float4*)W2s;
#pragma unroll
    for (int q = 0; q < 32; q++) {
        float v = h1[q];
#pragma unroll
        for (int p = 0; p < 4; p++) {
            float4 w = W2v[q * 4 + p];
            h2v[p].x += v * w.x;
            h2v[p].y += v * w.y;
            h2v[p].z += v * w.z;
            h2v[p].w += v * w.w;
        }
    }
    float z = B3s;
#pragma unroll
    for (int p = 0; p < 4; p++) {
        z += fmaxf(h2v[p].x, 0.f) * W3s[p * 4 + 0];
        z += fmaxf(h2v[p].y, 0.f) * W3s[p * 4 + 1];
        z += fmaxf(h2v[p].z, 0.f) * W3s[p * 4 + 2];
        z += fmaxf(h2v[p].w, 0.f) * W3s[p * 4 + 3];
    }

    float w = 1.f / (1.f + expf(-z));
    if (sb > 0.3f || db > 0.3f) w *= 2.f;
    float c = ea[(size_t)type * EE + j] * w;

    int pos = atomicAdd(&g_cur[type * NN + d], 1);
    g_srcA[(size_t)type * EE + pos] = s;
    g_cvalA[(size_t)type * EE + pos] = c;
}

// ---------------------------------------------------------------
// gather: updh[to][n] = fp16(x[to][n] + sum over CSR(e=1-to, dst n))
// ---------------------------------------------------------------
__global__ __launch_bounds__(256) void gather_kernel(const float* __restrict__ x)
{
    int to = blockIdx.y;
    int e = 1 - to;
    int lane = threadIdx.x & 31;
    int warp = threadIdx.x >> 5;
    int n = blockIdx.x * 8 + warp;
    if (n >= NN) return;

    int base = e * NN + n;
    int st = g_off[base];
    int en = g_cur[base];

    const uint2* tb = (const uint2*)(g_t + (size_t)e * NN * DD);
    const int* srcp = g_srcA + (size_t)e * EE;
    const float* cvp = g_cvalA + (size_t)e * EE;

    float4 acc = ((const float4*)(x + ((size_t)to * NN + n) * DD))[lane];

    int i = st;
    for (; i + 3 < en; i += 4) {
        int s0 = __ldg(srcp + i),     s1 = __ldg(srcp + i + 1);
        int s2 = __ldg(srcp + i + 2), s3 = __ldg(srcp + i + 3);
        float c0 = __ldg(cvp + i),     c1 = __ldg(cvp + i + 1);
        float c2 = __ldg(cvp + i + 2), c3 = __ldg(cvp + i + 3);
        uint2 h0 = tb[(size_t)s0 * 32 + lane];
        uint2 h1 = tb[(size_t)s1 * 32 + lane];
        uint2 h2 = tb[(size_t)s2 * 32 + lane];
        uint2 h3 = tb[(size_t)s3 * 32 + lane];
        float2 a0 = __half22float2(*(__half2*)&h0.x), b0 = __half22float2(*(__half2*)&h0.y);
        float2 a1 = __half22float2(*(__half2*)&h1.x), b1 = __half22float2(*(__half2*)&h1.y);
        float2 a2 = __half22float2(*(__half2*)&h2.x), b2 = __half22float2(*(__half2*)&h2.y);
        float2 a3 = __half22float2(*(__half2*)&h3.x), b3 = __half22float2(*(__half2*)&h3.y);
        acc.x += a0.x * c0; acc.y += a0.y * c0; acc.z += b0.x * c0; acc.w += b0.y * c0;
        acc.x += a1.x * c1; acc.y += a1.y * c1; acc.z += b1.x * c1; acc.w += b1.y * c1;
        acc.x += a2.x * c2; acc.y += a2.y * c2; acc.z += b2.x * c2; acc.w += b2.y * c2;
        acc.x += a3.x * c3; acc.y += a3.y * c3; acc.z += b3.x * c3; acc.w += b3.y * c3;
    }
    for (; i < en; i++) {
        int s0 = __ldg(srcp + i);
        float c0 = __ldg(cvp + i);
        uint2 h0 = tb[(size_t)s0 * 32 + lane];
        float2 a0 = __half22float2(*(__half2*)&h0.x), b0 = __half22float2(*(__half2*)&h0.y);
        acc.x += a0.x * c0; acc.y += a0.y * c0; acc.z += b0.x * c0; acc.w += b0.y * c0;
    }

    __half2 p0 = __floats2half2_rn(acc.x, acc.y);
    __half2 p1 = __floats2half2_rn(acc.z, acc.w);
    uint2 u;
    u.x = *(unsigned*)&p0;
    u.y = *(unsigned*)&p1;
    ((uint2*)(g_updh + ((size_t)to * NN + n) * DD))[lane] = u;
}

// ---------------------------------------------------------------
// nu (tensor core): out = relu(LN(updh @ nuW + nub) * g + b)
// ---------------------------------------------------------------
__global__ __launch_bounds__(256, 2) void nu_wmma_kernel(
    const float* __restrict__ nub,
    const float* __restrict__ lng, const float* __restrict__ lnb,
    float* __restrict__ out)
{
    extern __shared__ char smem_raw[];
    __half* Ah = (__half*)smem_raw;
    __half* Bh = Ah + 64 * APITCH;
    float*  Cs = (float*)(Bh + 128 * APITCH);
    float*  nubS = Cs + 64 * CPITCH;    // 128
    float*  gS   = nubS + 128;          // 128
    float*  lbS  = gS + 128;            // 128

    int type = blockIdx.y;
    int m0 = blockIdx.x * GTM;
    int tid = threadIdx.x;
    int wid = tid >> 5;
    int lane = tid & 31;

    copy_rows_h16(Ah, g_updh + (size_t)type * NN * DD, m0, NN, tid);
    copy_w_h16(Bh, g_nuWh + type * 128 * 128, tid);
    if (tid < 128) {
        nubS[tid] = nub[type * 128 + tid];
        gS[tid]   = lng[type * 128 + tid];
        lbS[tid]  = lnb[type * 128 + tid];
    }
    __syncthreads();

    wmma_tile64(Ah, Bh, Cs, wid);
    __syncthreads();

    // LN + relu epilogue: warp per 8 rows, lane owns 4 columns
    float* ob = out + (size_t)type * NN * DD;
    float4 bb = ((const float4*)nubS)[lane];
    float4 gg = ((const float4*)gS)[lane];
    float4 ll = ((const float4*)lbS)[lane];

    for (int rr = 0; rr < 8; rr++) {
        int r = wid * 8 + rr;
        int row = m0 + r;
        float4 c = ((const float4*)(Cs + r * CPITCH))[lane];
        c.x += bb.x; c.y += bb.y; c.z += bb.z; c.w += bb.w;
        float s = c.x + c.y + c.z + c.w;
#pragma unroll
        for (int o = 16; o > 0; o >>= 1) s += __shfl_xor_sync(0xffffffffu, s, o);
        float mu = s * (1.f / 128.f);
        float dx = c.x - mu, dy = c.y - mu, dz = c.z - mu, dw = c.w - mu;
        float v = dx * dx + dy * dy + dz * dz + dw * dw;
#pragma unroll
        for (int o = 16; o > 0; o >>= 1) v += __shfl_xor_sync(0xffffffffu, v, o);
        float rs = rsqrtf(v * (1.f / 128.f) + 1e-5f);
        if (row < NN) {
            float4 o4;
            o4.x = fmaxf(dx * rs * gg.x + ll.x, 0.f);
            o4.y = fmaxf(dy * rs * gg.y + ll.y, 0.f);
            o4.z = fmaxf(dz * rs * gg.z + ll.z, 0.f);
            o4.w = fmaxf(dw * rs * gg.w + ll.w, 0.f);
            ((float4*)(ob + (size_t)row * DD))[lane] = o4;
        }
    }
}

// ---------------------------------------------------------------
extern "C" void kernel_launch(void* const* d_in, const int* in_sizes, int n_in,
                              void* d_out, int out_size)
{
    const float* x    = (const float*)d_in[0];
    const int*   ei   = (const int*)d_in[1];
    const float* ea   = (const float*)d_in[2];
    const float* bdW1 = (const float*)d_in[3];
    const float* bdb1 = (const float*)d_in[4];
    const float* bdW2 = (const float*)d_in[5];
    const float* bdb2 = (const float*)d_in[6];
    const float* bdW3 = (const float*)d_in[7];
    const float* bdb3 = (const float*)d_in[8];
    const float* etW1 = (const float*)d_in[9];
    const float* etb1 = (const float*)d_in[10];
    const float* etW2 = (const float*)d_in[11];
    const float* etb2 = (const float*)d_in[12];
    const float* bwW1 = (const float*)d_in[13];
    const float* bwb1 = (const float*)d_in[14];
    const float* bwW2 = (const float*)d_in[15];
    const float* bwb2 = (const float*)d_in[16];
    const float* bwW3 = (const float*)d_in[17];
    const float* bwb3 = (const float*)d_in[18];
    const float* nuW  = (const float*)d_in[19];
    const float* nub  = (const float*)d_in[20];
    const float* lng  = (const float*)d_in[21];
    const float* lnb  = (const float*)d_in[22];
    float* out = (float*)d_out;

    // et: A + W1 + W2 (fp16), C aliases W1 region
    const int SMEM_ET = (64 + 128 + 128) * APITCH * 2;              // 87040
    // nu: A + W (fp16) + C (f32) + 3*128 f32
    const int SMEM_NU = (64 + 128) * APITCH * 2 + 64 * CPITCH * 4 + 3 * 128 * 4; // 87552
    cudaFuncSetAttribute((const void*)et_wmma_kernel,
                         cudaFuncAttributeMaxDynamicSharedMemorySize, SMEM_ET);
    cudaFuncSetAttribute((const void*)nu_wmma_kernel,
                         cudaFuncAttributeMaxDynamicSharedMemorySize, SMEM_NU);

    prep_kernel<<<(2 * NN + 255) / 256, 256>>>();
    convw_kernel<<<96, 256>>>(etW1, etW2, nuW);
    convx_kernel<<<(2 * NN * DD / 4 + 255) / 256, 256>>>(x);
    boundary_kernel<<<dim3((NN + 127) / 128, 2), 256>>>(x, bdW1, bdb1, bdW2, bdb2, bdW3, bdb3);
    et_wmma_kernel<<<dim3(NTILE, 2), 256, SMEM_ET>>>(etb1, etb2);
    hist_kernel<<<dim3((EE + 255) / 256, 2), 256>>>(ei);
    scan1_kernel<<<dim3(NCHUNK, 2), 1024>>>();
    scan2_kernel<<<1, 32>>>();
    scan3_kernel<<<dim3(NCHUNK, 2), 1024>>>();
    coef_order_kernel<<<dim3((EE + 255) / 256, 2), 256>>>(ei, ea, bwW1, bwb1, bwW2, bwb2, bwW3, bwb3);
    gather_kernel<<<dim3((NN + 7) / 8, 2), 256>>>(x);
    nu_wmma_kernel<<<dim3(NTILE, 2), 256, SMEM_NU>>>(nub, lng, lnb, out);
}